// round 14
// baseline (speedup 1.0000x reference)
#include <cuda_runtime.h>
#include <cuda_fp16.h>
#include <stdint.h>

#define BB 8
#define NN 2048
#define DD 256
#define BN (BB * NN)
#define TM 32            // PV chunk
#define TMS 64           // S-kernel chunk
#define NCH_S 16         // S chunks per half

// ---------------- device scratch (allocation-free) ----------------
__device__ __half g_xhi[BN * DD];        // X row-major fp16
__device__ __half g_xthi[BB * DD * NN];  // X^T [b][k][m] fp16
__device__ __half g_wthi[DD * DD];       // W^T [n][k] fp16
__device__ __half g_p[(size_t)BN * NN];  // P' = shifted exp * adj, fp16
__device__ float g_part[2 * BN * DD];    // Y (normalized) lives in first BN*DD
__device__ float g_den[2 * BN];          // per-half denominators (scaled)
__device__ float g_sh2[BN];              // per-row exponent shift (log2 units)

// ---------------- helpers ----------------
__device__ __forceinline__ uint32_t smem_u32(const void* p) {
    uint32_t a;
    asm("{ .reg .u64 t; cvta.to.shared.u64 t, %1; cvt.u32.u64 %0, t; }" : "=r"(a) : "l"(p));
    return a;
}
__device__ __forceinline__ void ldsm4(uint32_t* r, uint32_t a) {
    asm volatile("ldmatrix.sync.aligned.m8n8.x4.shared.b16 {%0,%1,%2,%3}, [%4];"
                 : "=r"(r[0]), "=r"(r[1]), "=r"(r[2]), "=r"(r[3]) : "r"(a));
}
__device__ __forceinline__ void mma16816(float* c, const uint32_t* a, const uint32_t* b) {
    asm volatile("mma.sync.aligned.m16n8k16.row.col.f32.f16.f16.f32 "
                 "{%0,%1,%2,%3},{%4,%5,%6,%7},{%8,%9},{%0,%1,%2,%3};"
                 : "+f"(c[0]), "+f"(c[1]), "+f"(c[2]), "+f"(c[3])
                 : "r"(a[0]), "r"(a[1]), "r"(a[2]), "r"(a[3]), "r"(b[0]), "r"(b[1]));
}
#define CPA16(dst, src) \
    asm volatile("cp.async.cg.shared.global [%0], [%1], 16;" :: "r"(dst), "l"(src))
#define CP_COMMIT() asm volatile("cp.async.commit_group;")
#define CP_WAIT(n)  asm volatile("cp.async.wait_group %0;" :: "n"(n))

__device__ __forceinline__ uint32_t cvt2h(float lo, float hi) {
    uint32_t r;
    asm("cvt.rn.f16x2.f32 %0, %1, %2;" : "=r"(r) : "f"(hi), "f"(lo));
    return r;
}
__device__ __forceinline__ float2 h2f2(uint32_t u) {
    __half2 h = *(__half2*)&u;
    return __half22float2(h);
}
__device__ __forceinline__ float fexp16s(float s, float sh) {
    float r;
    asm("ex2.approx.f32 %0, %1;" : "=f"(r) : "f"(fmaf(s, 0.09016844005556021f, -sh)));
    return r;
}

// ---------------- preprocessing ----------------
__global__ void __launch_bounds__(256) norm_kernel(const float* __restrict__ inp) {
    const int row = blockIdx.x * 8 + (threadIdx.x >> 5);
    const int lane = threadIdx.x & 31;
    const float4* p = (const float4*)(inp + (size_t)row * DD);
    const float4 a = p[lane];
    const float4 b = p[lane + 32];
    float s = a.x * a.x + a.y * a.y + a.z * a.z + a.w * a.w +
              b.x * b.x + b.y * b.y + b.z * b.z + b.w * b.w;
#pragma unroll
    for (int o = 16; o > 0; o >>= 1) s += __shfl_xor_sync(0xFFFFFFFFu, s, o);
    if (lane == 0)
        g_sh2[row] = (s * 0.0625f - 8.0f) * 1.44269504f;
}

__global__ void __launch_bounds__(256) split_x_kernel(const float* __restrict__ inp) {
    __shared__ float t[32][33];
    const int b = blockIdx.z;
    const int m0 = blockIdx.x * 32, k0 = blockIdx.y * 32;
    const int tx = threadIdx.x, ty = threadIdx.y;
    const float* src = inp + ((size_t)b * NN + m0) * DD + k0;
#pragma unroll
    for (int s = 0; s < 4; s++) {
        const int m = ty + 8 * s;
        const float v = src[(size_t)m * DD + tx];
        t[m][tx] = v;
        g_xhi[((size_t)b * NN + m0 + m) * DD + k0 + tx] = __float2half_rn(v);
    }
    __syncthreads();
#pragma unroll
    for (int s = 0; s < 4; s++) {
        const int c = ty + 8 * s;
        g_xthi[((size_t)b * DD + k0 + c) * NN + m0 + tx] = __float2half_rn(t[tx][c]);
    }
}

__global__ void __launch_bounds__(256) split_wt_kernel(const float* __restrict__ W) {
    __shared__ float t[32][33];
    const int k0 = blockIdx.x * 32, n0 = blockIdx.y * 32;
    const int tx = threadIdx.x, ty = threadIdx.y;
#pragma unroll
    for (int s = 0; s < 4; s++) t[ty + 8 * s][tx] = W[(size_t)(k0 + ty + 8 * s) * DD + n0 + tx];
    __syncthreads();
#pragma unroll
    for (int s = 0; s < 4; s++) {
        const int k = ty + 8 * s;
        g_wthi[(size_t)(n0 + tx) * DD + k0 + k] = __float2half_rn(t[k][tx]);
    }
}

// ---------------- S kernel: P' = ex2(QK^T*c - sh)*adj -> gmem fp16; den ----------------
// TM=64 chunks (16 per half), Q register-resident, K double-buffered.
#define SQ_Q   0u
#define SQ_K0  33792u
#define SQ_K1  67584u
#define SQ_DEN 101376u
#define SMEM_S 101888u

__global__ void __launch_bounds__(256, 2) s_kernel(const float* __restrict__ adj) {
    extern __shared__ char smem[];
    const uint32_t sb = smem_u32(smem);
    const int tid = threadIdx.x;
    const int wid = tid >> 5, lane = tid & 31;
    const int s = wid >> 1, hs = wid & 1;
    const int lane7 = lane & 7, l34 = (lane >> 3) & 1, l4 = lane >> 4;

    const int bb = blockIdx.x >> 6;
    const int i0 = ((blockIdx.x >> 1) & 31) * 64;
    const int half = blockIdx.x & 1;
    const int mbase = half * (NCH_S * TMS);

    const __half* __restrict__ xhiB = g_xhi + (size_t)bb * NN * DD;
    const float* __restrict__ adjB = adj + (size_t)bb * NN * NN;
    __half* __restrict__ pB = g_p + ((size_t)bb * NN + i0) * NN;

    float* den_sm = (float*)(smem + SQ_DEN);
    if (tid < 64) den_sm[tid] = 0.f;

    const int ldRow = tid >> 5, ldC16 = tid & 31;

    // Q (group 0), K0 (group 1), K1 (group 2)
#pragma unroll
    for (int it = 0; it < 8; it++) {
        const int row = ldRow + it * 8;
        CPA16(sb + SQ_Q + row * 528 + ldC16 * 16, xhiB + (size_t)(i0 + row) * DD + ldC16 * 8);
    }
    CP_COMMIT();
#pragma unroll
    for (int it = 0; it < 8; it++) {
        const int row = ldRow + it * 8;
        CPA16(sb + SQ_K0 + row * 528 + ldC16 * 16, xhiB + (size_t)(mbase + row) * DD + ldC16 * 8);
    }
    CP_COMMIT();
#pragma unroll
    for (int it = 0; it < 8; it++) {
        const int row = ldRow + it * 8;
        CPA16(sb + SQ_K1 + row * 528 + ldC16 * 16, xhiB + (size_t)(mbase + TMS + row) * DD + ldC16 * 8);
    }
    CP_COMMIT();

    CP_WAIT(2);          // Q ready
    __syncthreads();

    // hoist Q fragments into registers (64 regs)
    uint32_t qf[16][4];
    const uint32_t aQ = sb + SQ_Q + (uint32_t)(s * 16 + lane7 + l34 * 8) * 528 + l4 * 16;
#pragma unroll
    for (int kk = 0; kk < 16; kk++) ldsm4(qf[kk], aQ + kk * 32);

    const uint32_t kFrag = (uint32_t)((hs * 32 + l4 * 8 + lane7) * 528 + l34 * 16);
    const uint32_t kBuf[2] = {sb + SQ_K0, sb + SQ_K1};

    const int r0 = s * 16 + (lane >> 2);
    const int cb = hs * 32 + (lane & 3) * 2;
    const float sh0 = g_sh2[(size_t)bb * NN + i0 + r0];
    const float sh1 = g_sh2[(size_t)bb * NN + i0 + r0 + 8];
    float den0 = 0.f, den1 = 0.f;

    for (int ch = 0; ch < NCH_S; ch++) {
        const int m0 = mbase + ch * TMS;
        const int cur = ch & 1;
        CP_WAIT(1);
        __syncthreads();

        // adj prefetch
        const float* adjR0 = adjB + (size_t)(i0 + r0) * NN + m0 + cb;
        const float* adjR1 = adjR0 + 8 * NN;
        float2 aj0[4], aj1[4];
#pragma unroll
        for (int nt = 0; nt < 4; nt++) {
            aj0[nt] = __ldg((const float2*)(adjR0 + nt * 8));
            aj1[nt] = __ldg((const float2*)(adjR1 + nt * 8));
        }

        // S = Q*K (Q from regs), warp tile 16x32
        const uint32_t kB = kBuf[cur] + kFrag;
        float sacc[4][4];
#pragma unroll
        for (int i = 0; i < 4; i++)
#pragma unroll
            for (int j = 0; j < 4; j++) sacc[i][j] = 0.f;
#pragma unroll
        for (int kk = 0; kk < 16; kk++) {
            const uint32_t ko = kk * 32;
            uint32_t b0[4], b1[4];
            ldsm4(b0, kB + ko);
            ldsm4(b1, kB + 16 * 528 + ko);
            mma16816(sacc[0], qf[kk], b0 + 0);
            mma16816(sacc[1], qf[kk], b0 + 2);
            mma16816(sacc[2], qf[kk], b1 + 0);
            mma16816(sacc[3], qf[kk], b1 + 2);
        }

        // epilogue: P' -> gmem fp16; denom
#pragma unroll
        for (int nt = 0; nt < 4; nt++) {
            const float p00 = fexp16s(sacc[nt][0], sh0) * aj0[nt].x;
            const float p01 = fexp16s(sacc[nt][1], sh0) * aj0[nt].y;
            const float p10 = fexp16s(sacc[nt][2], sh1) * aj1[nt].x;
            const float p11 = fexp16s(sacc[nt][3], sh1) * aj1[nt].y;
            den0 += p00 + p01;
            den1 += p10 + p11;
            *(uint32_t*)(pB + (size_t)r0 * NN + m0 + cb + nt * 8) = cvt2h(p00, p01);
            *(uint32_t*)(pB + (size_t)(r0 + 8) * NN + m0 + cb + nt * 8) = cvt2h(p10, p11);
        }
        __syncthreads();   // all warps done reading K(ch)

        // issue K(ch+2)
        {
            const int mn = mbase + ((ch + 2) & (NCH_S - 1)) * TMS;
#pragma unroll
            for (int it = 0; it < 8; it++) {
                const int row = ldRow + it * 8;
                CPA16(kBuf[cur] + row * 528 + ldC16 * 16, xhiB + (size_t)(mn + row) * DD + ldC16 * 8);
            }
            CP_COMMIT();
        }
    }

    // denominators
    den0 += __shfl_xor_sync(0xFFFFFFFFu, den0, 1);
    den0 += __shfl_xor_sync(0xFFFFFFFFu, den0, 2);
    den1 += __shfl_xor_sync(0xFFFFFFFFu, den1, 1);
    den1 += __shfl_xor_sync(0xFFFFFFFFu, den1, 2);
    __syncthreads();
    if ((lane & 3) == 0) {
        atomicAdd(&den_sm[r0], den0);
        atomicAdd(&den_sm[r0 + 8], den1);
    }
    __syncthreads();
    if (tid < 64)
        g_den[(size_t)half * BN + (size_t)bb * NN + i0 + tid] = den_sm[tid];
}

// ---------------- PV kernel: Y = (P' @ X) / den  (k = 2048, single wave) ----------------
#define PV_V0  0u
#define PV_V1  20480u
#define PV_P0  40960u
#define PV_P1  46080u
#define PV_DEN 51200u
#define SMEM_PV 51456u

__global__ void __launch_bounds__(256, 2) pv_kernel() {
    extern __shared__ char smem[];
    const uint32_t sb = smem_u32(smem);
    const int tid = threadIdx.x;
    const int wid = tid >> 5, lane = tid & 31;
    const int rs = wid >> 2, cs = wid & 3;
    const int lane7 = lane & 7, l34 = (lane >> 3) & 1, l4 = lane >> 4;

    const int bb = blockIdx.x >> 5;
    const int i0 = (blockIdx.x & 31) * 64;

    const __half* __restrict__ xthiB = g_xthi + (size_t)bb * DD * NN;
    const __half* __restrict__ pB = g_p + ((size_t)bb * NN + i0) * NN;

    const int ldRowV = tid >> 2, ldC16V = tid & 3;
    const int ldRowP = tid >> 2, ldC16P = tid & 3;

    // G0: V(0), P(0)
#pragma unroll
    for (int it = 0; it < 4; it++) {
        const int row = ldRowV + it * 64;
        CPA16(sb + PV_V0 + row * 80 + ldC16V * 16, xthiB + (size_t)row * NN + ldC16V * 8);
    }
    CPA16(sb + PV_P0 + ldRowP * 80 + ldC16P * 16, pB + (size_t)ldRowP * NN + ldC16P * 8);
    CP_COMMIT();
    // G1: V(1), P(1)
#pragma unroll
    for (int it = 0; it < 4; it++) {
        const int row = ldRowV + it * 64;
        CPA16(sb + PV_V1 + row * 80 + ldC16V * 16, xthiB + (size_t)row * NN + TM + ldC16V * 8);
    }
    CPA16(sb + PV_P1 + ldRowP * 80 + ldC16P * 16, pB + (size_t)ldRowP * NN + TM + ldC16P * 8);
    CP_COMMIT();

    float* invd_s = (float*)(smem + PV_DEN);
    if (tid < 64) {
        const size_t gi = (size_t)bb * NN + i0 + tid;
        const float d = g_den[gi] + g_den[BN + gi];
        const float eps = 1e-10f * exp2f(-g_sh2[gi]);
        invd_s[tid] = 1.0f / (d + eps);
    }

    const uint32_t pFrag = (uint32_t)((rs * 32 + lane7 + l34 * 8) * 80 + l4 * 16);
    const uint32_t vFrag = (uint32_t)((cs * 64 + l4 * 8 + lane7) * 80 + l34 * 16);
    const uint32_t pBuf[2] = {sb + PV_P0, sb + PV_P1};
    const uint32_t vBuf[2] = {sb + PV_V0, sb + PV_V1};

    float oacc[16][4];
#pragma unroll
    for (int i = 0; i < 16; i++)
#pragma unroll
        for (int j = 0; j < 4; j++) oacc[i][j] = 0.f;

    for (int ch = 0; ch < 64; ch++) {
        const int cur = ch & 1;
        CP_WAIT(1);
        __syncthreads();

        const uint32_t pA = pBuf[cur] + pFrag;
        const uint32_t vB = vBuf[cur] + vFrag;
#pragma unroll
        for (int kk = 0; kk < 2; kk++) {
            const uint32_t ko = kk * 32;
            uint32_t a0[4], a1[4];
            ldsm4(a0, pA + ko);
            ldsm4(a1, pA + 16 * 80 + ko);
#pragma unroll
            for (int j = 0; j < 4; j++) {
                uint32_t bv[4];
                ldsm4(bv, vB + j * (16 * 80) + ko);
                mma16816(oacc[j * 2 + 0], a0, bv + 0);
                mma16816(oacc[j * 2 + 1], a0, bv + 2);
                mma16816(oacc[8 + j * 2 + 0], a1, bv + 0);
                mma16816(oacc[8 + j * 2 + 1], a1, bv + 2);
            }
        }
        __syncthreads();

        {
            const int mn = ((ch + 2) & 63) * TM;
#pragma unroll
            for (int it = 0; it < 4; it++) {
                const int row = ldRowV + it * 64;
                CPA16(vBuf[cur] + row * 80 + ldC16V * 16, xthiB + (size_t)row * NN + mn + ldC16V * 8);
            }
            CPA16(pBuf[cur] + ldRowP * 80 + ldC16P * 16, pB + (size_t)ldRowP * NN + mn + ldC16P * 8);
            CP_COMMIT();
        }
    }

    float* yB = g_part + ((size_t)bb * NN + i0) * DD;
#pragma unroll
    for (int t = 0; t < 2; t++) {
        const int rloc = rs * 32 + t * 16 + (lane >> 2);
        const float iv0 = invd_s[rloc];
        const float iv1 = invd_s[rloc + 8];
#pragma unroll
        for (int j = 0; j < 4; j++) {
#pragma unroll
            for (int nn = 0; nn < 2; nn++) {
                const int idx = t * 8 + j * 2 + nn;
                const int col = cs * 64 + j * 16 + nn * 8 + (lane & 3) * 2;
                *(float2*)(yB + (size_t)rloc * DD + col) =
                    make_float2(oacc[idx][0] * iv0, oacc[idx][1] * iv0);
                *(float2*)(yB + (size_t)(rloc + 8) * DD + col) =
                    make_float2(oacc[idx][2] * iv1, oacc[idx][3] * iv1);
            }
        }
    }
}

// ---------------- final: out = leaky_relu(Y @ W + b) ----------------
#define YW_YHI 0u
#define YW_YLO 33792u
#define YW_W0  67584u
#define YW_W1  88064u
#define SMEM_YW 108544u

__global__ void __launch_bounds__(256, 2) ywb_kernel(const float* __restrict__ bvec,
                                                     float* __restrict__ out) {
    extern __shared__ char smem[];
    const uint32_t sb = smem_u32(smem);
    const int tid = threadIdx.x;
    const int wid = tid >> 5, lane = tid & 31;
    const int s = wid >> 1, hs = wid & 1;
    const int lane7 = lane & 7, l34 = (lane >> 3) & 1, l4 = lane >> 4;
    const int R0 = blockIdx.x * 64;

    const uint32_t wOff[2] = {YW_W0, YW_W1};
    const int ldRow = tid >> 2, ldC16 = tid & 3;

#pragma unroll
    for (int it = 0; it < 4; it++) {
        const int row = ldRow + it * 64;
        CPA16(sb + YW_W0 + row * 80 + ldC16 * 16, g_wthi + (size_t)row * DD + ldC16 * 8);
    }
    CP_COMMIT();

#pragma unroll
    for (int it = 0; it < 16; it++) {
        const int idx = it * 256 + tid;
        const int row = idx >> 6, c4 = idx & 63;
        const float4 v = *(const float4*)(g_part + (size_t)(R0 + row) * DD + c4 * 4);
        const uint32_t h0 = cvt2h(v.x, v.y), h1 = cvt2h(v.z, v.w);
        const float2 f0 = h2f2(h0), f1 = h2f2(h1);
        const uint32_t l0 = cvt2h(v.x - f0.x, v.y - f0.y);
        const uint32_t l1 = cvt2h(v.z - f1.x, v.w - f1.y);
        *(uint2*)(smem + YW_YHI + row * 528 + c4 * 8) = make_uint2(h0, h1);
        *(uint2*)(smem + YW_YLO + row * 528 + c4 * 8) = make_uint2(l0, l1);
    }

    const int aRow = s * 16 + lane7 + l34 * 8;
    const uint32_t aYhi = sb + YW_YHI + aRow * 528 + l4 * 16;
    const uint32_t aYlo = sb + YW_YLO + aRow * 528 + l4 * 16;
    const int wRow = hs * 128 + l4 * 8 + lane7;
    const uint32_t wFragBase = (uint32_t)(wRow * 80 + l34 * 16);

    float oacc[16][4];
#pragma unroll
    for (int i = 0; i < 16; i++)
#pragma unroll
        for (int j = 0; j < 4; j++) oacc[i][j] = 0.f;

    for (int kc = 0; kc < 8; kc++) {
        if (kc < 7) {
            const uint32_t wb = wOff[(kc + 1) & 1];
#pragma unroll
            for (int it = 0; it < 4; it++) {
                const int row = ldRow + it * 64;
                CPA16(sb + wb + row * 80 + ldC16 * 16, g_wthi + (size_t)row * DD + (kc + 1) * 32 + ldC16 * 8);
            }
            CP_COMMIT();
            CP_WAIT(1);
        } else {
            CP_WAIT(0);
        }
        __syncthreads();

        const uint32_t bW = sb + wOff[kc & 1] + wFragBase;
#pragma unroll
        for (int kk = 0; kk < 2; kk++) {
            const uint32_t koA = (kc * 32 + kk * 16) * 2;
            const uint32_t koB = kk * 32;
            uint32_t ah[4], al[4];
            ldsm4(ah, aYhi + koA);
            ldsm4(al, aYlo + koA);
#pragma unroll
            for (int nt = 0; nt < 8; nt++) {
                uint32_t bh[4];
                ldsm4(bh, bW + nt * (16 * 80) + koB);
                mma16816(oacc[nt * 2], ah, bh + 0);
                mma16816(oacc[nt * 2 + 1], ah, bh + 2);
                mma16816(oacc[nt * 2], al, bh + 0);
                mma16816(oacc[nt * 2 + 1], al, bh + 2);
            }
        }
        __syncthreads();
    }

    const int r0 = s * 16 + (lane >> 2);
    const int c0 = hs * 128 + (lane & 3) * 2;
    float* oR0 = out + (size_t)(R0 + r0) * DD + c0;
    float* oR1 = oR0 + 8 * DD;
#pragma unroll
    for (int nt = 0; nt < 16; nt++) {
        const float2 bv = *(const float2*)(bvec + c0 + nt * 8);
        float v0 = oacc[nt][0] + bv.x, v1 = oacc[nt][1] + bv.y;
        float v2 = oacc[nt][2] + bv.x, v3 = oacc[nt][3] + bv.y;
        v0 = v0 > 0.f ? v0 : 0.01f * v0;
        v1 = v1 > 0.f ? v1 : 0.01f * v1;
        v2 = v2 > 0.f ? v2 : 0.01f * v2;
        v3 = v3 > 0.f ? v3 : 0.01f * v3;
        *(float2*)(oR0 + nt * 8) = make_float2(v0, v1);
        *(float2*)(oR1 + nt * 8) = make_float2(v2, v3);
    }
}

// ---------------------------------------------------------------------------
extern "C" void kernel_launch(void* const* d_in, const int* in_sizes, int n_in,
                              void* d_out, int out_size) {
    const float* inp = (const float*)d_in[0];
    const float* adj = (const float*)d_in[1];
    const float* W = (const float*)d_in[2];
    const float* b = (const float*)d_in[3];
    float* out = (float*)d_out;

    norm_kernel<<<BN / 8, 256>>>(inp);
    split_x_kernel<<<dim3(NN / 32, DD / 32, BB), dim3(32, 8)>>>(inp);
    split_wt_kernel<<<dim3(DD / 32, DD / 32), dim3(32, 8)>>>(W);

    cudaFuncSetAttribute(s_kernel, cudaFuncAttributeMaxDynamicSharedMemorySize, SMEM_S);
    s_kernel<<<BB * 32 * 2, 256, SMEM_S>>>(adj);

    cudaFuncSetAttribute(pv_kernel, cudaFuncAttributeMaxDynamicSharedMemorySize, SMEM_PV);
    pv_kernel<<<BB * 32, 256, SMEM_PV>>>();

    cudaFuncSetAttribute(ywb_kernel, cudaFuncAttributeMaxDynamicSharedMemorySize, SMEM_YW);
    ywb_kernel<<<BN / 64, 256, SMEM_YW>>>(b, out);
}

// round 15
// speedup vs baseline: 1.0641x; 1.0641x over previous
#include <cuda_runtime.h>
#include <cuda_fp16.h>
#include <stdint.h>

#define BB 8
#define NN 2048
#define DD 256
#define BN (BB * NN)
#define TM 32            // PV chunk
#define TMS 64           // S-kernel chunk
#define NCH_S 16         // S chunks per half

// ---------------- device scratch (allocation-free) ----------------
__device__ __half g_xhi[BN * DD];        // X row-major fp16
__device__ __half g_xthi[BB * DD * NN];  // X^T [b][k][m] fp16
__device__ __half g_wthi[DD * DD];       // W^T [n][k] fp16
__device__ __half g_p[(size_t)BN * NN];  // P' = shifted exp * adj, fp16
__device__ float g_part[2 * BN * DD];    // Y (normalized) lives in first BN*DD
__device__ float g_den[2 * BN];          // per-half denominators (scaled)
__device__ float g_sh2[BN];              // per-row exponent shift (log2 units)

// ---------------- helpers ----------------
__device__ __forceinline__ uint32_t smem_u32(const void* p) {
    uint32_t a;
    asm("{ .reg .u64 t; cvta.to.shared.u64 t, %1; cvt.u32.u64 %0, t; }" : "=r"(a) : "l"(p));
    return a;
}
__device__ __forceinline__ void ldsm4(uint32_t* r, uint32_t a) {
    asm volatile("ldmatrix.sync.aligned.m8n8.x4.shared.b16 {%0,%1,%2,%3}, [%4];"
                 : "=r"(r[0]), "=r"(r[1]), "=r"(r[2]), "=r"(r[3]) : "r"(a));
}
__device__ __forceinline__ void mma16816(float* c, const uint32_t* a, const uint32_t* b) {
    asm volatile("mma.sync.aligned.m16n8k16.row.col.f32.f16.f16.f32 "
                 "{%0,%1,%2,%3},{%4,%5,%6,%7},{%8,%9},{%0,%1,%2,%3};"
                 : "+f"(c[0]), "+f"(c[1]), "+f"(c[2]), "+f"(c[3])
                 : "r"(a[0]), "r"(a[1]), "r"(a[2]), "r"(a[3]), "r"(b[0]), "r"(b[1]));
}
#define CPA16(dst, src) \
    asm volatile("cp.async.cg.shared.global [%0], [%1], 16;" :: "r"(dst), "l"(src))
#define CP_COMMIT() asm volatile("cp.async.commit_group;")
#define CP_WAIT(n)  asm volatile("cp.async.wait_group %0;" :: "n"(n))

__device__ __forceinline__ uint32_t cvt2h(float lo, float hi) {
    uint32_t r;
    asm("cvt.rn.f16x2.f32 %0, %1, %2;" : "=r"(r) : "f"(hi), "f"(lo));
    return r;
}
__device__ __forceinline__ float2 h2f2(uint32_t u) {
    __half2 h = *(__half2*)&u;
    return __half22float2(h);
}
__device__ __forceinline__ float fexp16s(float s, float sh) {
    float r;
    asm("ex2.approx.f32 %0, %1;" : "=f"(r) : "f"(fmaf(s, 0.09016844005556021f, -sh)));
    return r;
}

// ---------------- preprocessing ----------------
__global__ void __launch_bounds__(256) norm_kernel(const float* __restrict__ inp) {
    const int row = blockIdx.x * 8 + (threadIdx.x >> 5);
    const int lane = threadIdx.x & 31;
    const float4* p = (const float4*)(inp + (size_t)row * DD);
    const float4 a = p[lane];
    const float4 b = p[lane + 32];
    float s = a.x * a.x + a.y * a.y + a.z * a.z + a.w * a.w +
              b.x * b.x + b.y * b.y + b.z * b.z + b.w * b.w;
#pragma unroll
    for (int o = 16; o > 0; o >>= 1) s += __shfl_xor_sync(0xFFFFFFFFu, s, o);
    if (lane == 0)
        g_sh2[row] = (s * 0.0625f - 8.0f) * 1.44269504f;
}

__global__ void __launch_bounds__(256) split_x_kernel(const float* __restrict__ inp) {
    __shared__ float t[32][33];
    const int b = blockIdx.z;
    const int m0 = blockIdx.x * 32, k0 = blockIdx.y * 32;
    const int tx = threadIdx.x, ty = threadIdx.y;
    const float* src = inp + ((size_t)b * NN + m0) * DD + k0;
#pragma unroll
    for (int s = 0; s < 4; s++) {
        const int m = ty + 8 * s;
        const float v = src[(size_t)m * DD + tx];
        t[m][tx] = v;
        g_xhi[((size_t)b * NN + m0 + m) * DD + k0 + tx] = __float2half_rn(v);
    }
    __syncthreads();
#pragma unroll
    for (int s = 0; s < 4; s++) {
        const int c = ty + 8 * s;
        g_xthi[((size_t)b * DD + k0 + c) * NN + m0 + tx] = __float2half_rn(t[tx][c]);
    }
}

__global__ void __launch_bounds__(256) split_wt_kernel(const float* __restrict__ W) {
    __shared__ float t[32][33];
    const int k0 = blockIdx.x * 32, n0 = blockIdx.y * 32;
    const int tx = threadIdx.x, ty = threadIdx.y;
#pragma unroll
    for (int s = 0; s < 4; s++) t[ty + 8 * s][tx] = W[(size_t)(k0 + ty + 8 * s) * DD + n0 + tx];
    __syncthreads();
#pragma unroll
    for (int s = 0; s < 4; s++) {
        const int k = ty + 8 * s;
        g_wthi[(size_t)(n0 + tx) * DD + k0 + k] = __float2half_rn(t[k][tx]);
    }
}

// ---------------- S kernel: P' = ex2(QK^T*c - sh)*adj -> gmem; den ----------------
// TM=64 chunks, Q hoisted to regs, K triple-buffered (ring reuses Q's smem),
// ONE CTA barrier per chunk.
#define SQ_B0  0u
#define SQ_B1  33792u
#define SQ_B2  67584u
#define SQ_DEN 101376u
#define SMEM_S 101888u

__global__ void __launch_bounds__(256, 2) s_kernel(const float* __restrict__ adj) {
    extern __shared__ char smem[];
    const uint32_t sb = smem_u32(smem);
    const int tid = threadIdx.x;
    const int wid = tid >> 5, lane = tid & 31;
    const int s = wid >> 1, hs = wid & 1;
    const int lane7 = lane & 7, l34 = (lane >> 3) & 1, l4 = lane >> 4;

    const int bb = blockIdx.x >> 6;
    const int i0 = ((blockIdx.x >> 1) & 31) * 64;
    const int half = blockIdx.x & 1;
    const int mbase = half * (NCH_S * TMS);

    const __half* __restrict__ xhiB = g_xhi + (size_t)bb * NN * DD;
    const float* __restrict__ adjB = adj + (size_t)bb * NN * NN;
    __half* __restrict__ pB = g_p + ((size_t)bb * NN + i0) * NN;

    float* den_sm = (float*)(smem + SQ_DEN);
    if (tid < 64) den_sm[tid] = 0.f;

    const int ldRow = tid >> 5, ldC16 = tid & 31;
    const uint32_t kRing[3] = {sb + SQ_B0, sb + SQ_B1, sb + SQ_B2};

    // Q -> ring[2] (group 0), K(0) -> ring[0] (group 1), K(1) -> ring[1] (group 2)
#pragma unroll
    for (int it = 0; it < 8; it++) {
        const int row = ldRow + it * 8;
        CPA16(kRing[2] + row * 528 + ldC16 * 16, xhiB + (size_t)(i0 + row) * DD + ldC16 * 8);
    }
    CP_COMMIT();
#pragma unroll
    for (int it = 0; it < 8; it++) {
        const int row = ldRow + it * 8;
        CPA16(kRing[0] + row * 528 + ldC16 * 16, xhiB + (size_t)(mbase + row) * DD + ldC16 * 8);
    }
    CP_COMMIT();
#pragma unroll
    for (int it = 0; it < 8; it++) {
        const int row = ldRow + it * 8;
        CPA16(kRing[1] + row * 528 + ldC16 * 16, xhiB + (size_t)(mbase + TMS + row) * DD + ldC16 * 8);
    }
    CP_COMMIT();

    CP_WAIT(2);          // Q ready
    __syncthreads();

    // hoist Q fragments into registers (64 regs); ring[2] becomes free after sync1(ch=0)
    uint32_t qf[16][4];
    const uint32_t aQ = kRing[2] + (uint32_t)(s * 16 + lane7 + l34 * 8) * 528 + l4 * 16;
#pragma unroll
    for (int kk = 0; kk < 16; kk++) ldsm4(qf[kk], aQ + kk * 32);

    const uint32_t kFrag = (uint32_t)((hs * 32 + l4 * 8 + lane7) * 528 + l34 * 16);

    const int r0 = s * 16 + (lane >> 2);
    const int cb = hs * 32 + (lane & 3) * 2;
    const float sh0 = g_sh2[(size_t)bb * NN + i0 + r0];
    const float sh1 = g_sh2[(size_t)bb * NN + i0 + r0 + 8];
    float den0 = 0.f, den1 = 0.f;

    int bcur = 0;  // = ch % 3
    for (int ch = 0; ch < NCH_S; ch++) {
        const int m0 = mbase + ch * TMS;
        CP_WAIT(1);          // K(ch) done (K(ch+1) may be in flight)
        __syncthreads();     // single barrier: all warps finished chunk ch-1
                             // (also covers Q-hoist completion at ch=0)

        // issue K(ch+2) -> ring[(ch+2)%3] = ring[(ch-1)%3] (drained by the barrier)
        {
            const int bnext = (bcur + 2 >= 3) ? bcur - 1 : bcur + 2;
            const int mn = mbase + ((ch + 2) & (NCH_S - 1)) * TMS;
#pragma unroll
            for (int it = 0; it < 8; it++) {
                const int row = ldRow + it * 8;
                CPA16(kRing[bnext] + row * 528 + ldC16 * 16, xhiB + (size_t)(mn + row) * DD + ldC16 * 8);
            }
            CP_COMMIT();
        }

        // adj prefetch (hidden under S MMAs)
        const float* adjR0 = adjB + (size_t)(i0 + r0) * NN + m0 + cb;
        const float* adjR1 = adjR0 + 8 * NN;
        float2 aj0[4], aj1[4];
#pragma unroll
        for (int nt = 0; nt < 4; nt++) {
            aj0[nt] = __ldg((const float2*)(adjR0 + nt * 8));
            aj1[nt] = __ldg((const float2*)(adjR1 + nt * 8));
        }

        // S = Q*K (Q from regs), warp tile 16x32
        const uint32_t kB = kRing[bcur] + kFrag;
        float sacc[4][4];
#pragma unroll
        for (int i = 0; i < 4; i++)
#pragma unroll
            for (int j = 0; j < 4; j++) sacc[i][j] = 0.f;
#pragma unroll
        for (int kk = 0; kk < 16; kk++) {
            const uint32_t ko = kk * 32;
            uint32_t b0[4], b1[4];
            ldsm4(b0, kB + ko);
            ldsm4(b1, kB + 16 * 528 + ko);
            mma16816(sacc[0], qf[kk], b0 + 0);
            mma16816(sacc[1], qf[kk], b0 + 2);
            mma16816(sacc[2], qf[kk], b1 + 0);
            mma16816(sacc[3], qf[kk], b1 + 2);
        }

        // epilogue: P' -> gmem fp16; denom
#pragma unroll
        for (int nt = 0; nt < 4; nt++) {
            const float p00 = fexp16s(sacc[nt][0], sh0) * aj0[nt].x;
            const float p01 = fexp16s(sacc[nt][1], sh0) * aj0[nt].y;
            const float p10 = fexp16s(sacc[nt][2], sh1) * aj1[nt].x;
            const float p11 = fexp16s(sacc[nt][3], sh1) * aj1[nt].y;
            den0 += p00 + p01;
            den1 += p10 + p11;
            *(uint32_t*)(pB + (size_t)r0 * NN + m0 + cb + nt * 8) = cvt2h(p00, p01);
            *(uint32_t*)(pB + (size_t)(r0 + 8) * NN + m0 + cb + nt * 8) = cvt2h(p10, p11);
        }

        bcur = (bcur + 1 >= 3) ? 0 : bcur + 1;
    }

    // denominators
    den0 += __shfl_xor_sync(0xFFFFFFFFu, den0, 1);
    den0 += __shfl_xor_sync(0xFFFFFFFFu, den0, 2);
    den1 += __shfl_xor_sync(0xFFFFFFFFu, den1, 1);
    den1 += __shfl_xor_sync(0xFFFFFFFFu, den1, 2);
    __syncthreads();
    if ((lane & 3) == 0) {
        atomicAdd(&den_sm[r0], den0);
        atomicAdd(&den_sm[r0 + 8], den1);
    }
    __syncthreads();
    if (tid < 64)
        g_den[(size_t)half * BN + (size_t)bb * NN + i0 + tid] = den_sm[tid];
}

// ---------------- PV kernel: Y = (P' @ X) / den, V/P triple-buffered ----------------
#define PV_V0  0u
#define PV_V1  20480u
#define PV_V2  40960u
#define PV_P0  61440u
#define PV_P1  66560u
#define PV_P2  71680u
#define PV_DEN 76800u
#define SMEM_PV 77056u

__global__ void __launch_bounds__(256, 2) pv_kernel() {
    extern __shared__ char smem[];
    const uint32_t sb = smem_u32(smem);
    const int tid = threadIdx.x;
    const int wid = tid >> 5, lane = tid & 31;
    const int rs = wid >> 2, cs = wid & 3;
    const int lane7 = lane & 7, l34 = (lane >> 3) & 1, l4 = lane >> 4;

    const int bb = blockIdx.x >> 5;
    const int i0 = (blockIdx.x & 31) * 64;

    const __half* __restrict__ xthiB = g_xthi + (size_t)bb * DD * NN;
    const __half* __restrict__ pB = g_p + ((size_t)bb * NN + i0) * NN;

    const int ldRowV = tid >> 2, ldC16V = tid & 3;
    const int ldRowP = tid >> 2, ldC16P = tid & 3;

    const uint32_t vRing[3] = {sb + PV_V0, sb + PV_V1, sb + PV_V2};
    const uint32_t pRing[3] = {sb + PV_P0, sb + PV_P1, sb + PV_P2};

    // G0: V(0), P(0); G1: V(1), P(1)
#pragma unroll
    for (int it = 0; it < 4; it++) {
        const int row = ldRowV + it * 64;
        CPA16(vRing[0] + row * 80 + ldC16V * 16, xthiB + (size_t)row * NN + ldC16V * 8);
    }
    CPA16(pRing[0] + ldRowP * 80 + ldC16P * 16, pB + (size_t)ldRowP * NN + ldC16P * 8);
    CP_COMMIT();
#pragma unroll
    for (int it = 0; it < 4; it++) {
        const int row = ldRowV + it * 64;
        CPA16(vRing[1] + row * 80 + ldC16V * 16, xthiB + (size_t)row * NN + TM + ldC16V * 8);
    }
    CPA16(pRing[1] + ldRowP * 80 + ldC16P * 16, pB + (size_t)ldRowP * NN + TM + ldC16P * 8);
    CP_COMMIT();

    float* invd_s = (float*)(smem + PV_DEN);
    if (tid < 64) {
        const size_t gi = (size_t)bb * NN + i0 + tid;
        const float d = g_den[gi] + g_den[BN + gi];
        const float eps = 1e-10f * exp2f(-g_sh2[gi]);
        invd_s[tid] = 1.0f / (d + eps);
    }

    const uint32_t pFrag = (uint32_t)((rs * 32 + lane7 + l34 * 8) * 80 + l4 * 16);
    const uint32_t vFrag = (uint32_t)((cs * 64 + l4 * 8 + lane7) * 80 + l34 * 16);

    float oacc[16][4];
#pragma unroll
    for (int i = 0; i < 16; i++)
#pragma unroll
        for (int j = 0; j < 4; j++) oacc[i][j] = 0.f;

    int bcur = 0;
    for (int ch = 0; ch < 64; ch++) {
        CP_WAIT(1);
        __syncthreads();   // single barrier per chunk

        // issue (V,P)(ch+2) -> ring[(ch+2)%3] (drained: read at chunk ch-1)
        {
            const int bnext = (bcur + 2 >= 3) ? bcur - 1 : bcur + 2;
            const int mn = ((ch + 2) & 63) * TM;
#pragma unroll
            for (int it = 0; it < 4; it++) {
                const int row = ldRowV + it * 64;
                CPA16(vRing[bnext] + row * 80 + ldC16V * 16, xthiB + (size_t)row * NN + mn + ldC16V * 8);
            }
            CPA16(pRing[bnext] + ldRowP * 80 + ldC16P * 16, pB + (size_t)ldRowP * NN + mn + ldC16P * 8);
            CP_COMMIT();
        }

        const uint32_t pA = pRing[bcur] + pFrag;
        const uint32_t vB = vRing[bcur] + vFrag;
#pragma unroll
        for (int kk = 0; kk < 2; kk++) {
            const uint32_t ko = kk * 32;
            uint32_t a0[4], a1[4];
            ldsm4(a0, pA + ko);
            ldsm4(a1, pA + 16 * 80 + ko);
#pragma unroll
            for (int j = 0; j < 4; j++) {
                uint32_t bv[4];
                ldsm4(bv, vB + j * (16 * 80) + ko);
                mma16816(oacc[j * 2 + 0], a0, bv + 0);
                mma16816(oacc[j * 2 + 1], a0, bv + 2);
                mma16816(oacc[8 + j * 2 + 0], a1, bv + 0);
                mma16816(oacc[8 + j * 2 + 1], a1, bv + 2);
            }
        }

        bcur = (bcur + 1 >= 3) ? 0 : bcur + 1;
    }

    float* yB = g_part + ((size_t)bb * NN + i0) * DD;
#pragma unroll
    for (int t = 0; t < 2; t++) {
        const int rloc = rs * 32 + t * 16 + (lane >> 2);
        const float iv0 = invd_s[rloc];
        const float iv1 = invd_s[rloc + 8];
#pragma unroll
        for (int j = 0; j < 4; j++) {
#pragma unroll
            for (int nn = 0; nn < 2; nn++) {
                const int idx = t * 8 + j * 2 + nn;
                const int col = cs * 64 + j * 16 + nn * 8 + (lane & 3) * 2;
                *(float2*)(yB + (size_t)rloc * DD + col) =
                    make_float2(oacc[idx][0] * iv0, oacc[idx][1] * iv0);
                *(float2*)(yB + (size_t)(rloc + 8) * DD + col) =
                    make_float2(oacc[idx][2] * iv1, oacc[idx][3] * iv1);
            }
        }
    }
}

// ---------------- final: out = leaky_relu(Y @ W + b) ----------------
#define YW_YHI 0u
#define YW_YLO 33792u
#define YW_W0  67584u
#define YW_W1  88064u
#define SMEM_YW 108544u

__global__ void __launch_bounds__(256, 2) ywb_kernel(const float* __restrict__ bvec,
                                                     float* __restrict__ out) {
    extern __shared__ char smem[];
    const uint32_t sb = smem_u32(smem);
    const int tid = threadIdx.x;
    const int wid = tid >> 5, lane = tid & 31;
    const int s = wid >> 1, hs = wid & 1;
    const int lane7 = lane & 7, l34 = (lane >> 3) & 1, l4 = lane >> 4;
    const int R0 = blockIdx.x * 64;

    const uint32_t wOff[2] = {YW_W0, YW_W1};
    const int ldRow = tid >> 2, ldC16 = tid & 3;

#pragma unroll
    for (int it = 0; it < 4; it++) {
        const int row = ldRow + it * 64;
        CPA16(sb + YW_W0 + row * 80 + ldC16 * 16, g_wthi + (size_t)row * DD + ldC16 * 8);
    }
    CP_COMMIT();

#pragma unroll
    for (int it = 0; it < 16; it++) {
        const int idx = it * 256 + tid;
        const int row = idx >> 6, c4 = idx & 63;
        const float4 v = *(const float4*)(g_part + (size_t)(R0 + row) * DD + c4 * 4);
        const uint32_t h0 = cvt2h(v.x, v.y), h1 = cvt2h(v.z, v.w);
        const float2 f0 = h2f2(h0), f1 = h2f2(h1);
        const uint32_t l0 = cvt2h(v.x - f0.x, v.y - f0.y);
        const uint32_t l1 = cvt2h(v.z - f1.x, v.w - f1.y);
        *(uint2*)(smem + YW_YHI + row * 528 + c4 * 8) = make_uint2(h0, h1);
        *(uint2*)(smem + YW_YLO + row * 528 + c4 * 8) = make_uint2(l0, l1);
    }

    const int aRow = s * 16 + lane7 + l34 * 8;
    const uint32_t aYhi = sb + YW_YHI + aRow * 528 + l4 * 16;
    const uint32_t aYlo = sb + YW_YLO + aRow * 528 + l4 * 16;
    const int wRow = hs * 128 + l4 * 8 + lane7;
    const uint32_t wFragBase = (uint32_t)(wRow * 80 + l34 * 16);

    float oacc[16][4];
#pragma unroll
    for (int i = 0; i < 16; i++)
#pragma unroll
        for (int j = 0; j < 4; j++) oacc[i][j] = 0.f;

    for (int kc = 0; kc < 8; kc++) {
        if (kc < 7) {
            const uint32_t wb = wOff[(kc + 1) & 1];
#pragma unroll
            for (int it = 0; it < 4; it++) {
                const int row = ldRow + it * 64;
                CPA16(sb + wb + row * 80 + ldC16 * 16, g_wthi + (size_t)row * DD + (kc + 1) * 32 + ldC16 * 8);
            }
            CP_COMMIT();
            CP_WAIT(1);
        } else {
            CP_WAIT(0);
        }
        __syncthreads();

        const uint32_t bW = sb + wOff[kc & 1] + wFragBase;
#pragma unroll
        for (int kk = 0; kk < 2; kk++) {
            const uint32_t koA = (kc * 32 + kk * 16) * 2;
            const uint32_t koB = kk * 32;
            uint32_t ah[4], al[4];
            ldsm4(ah, aYhi + koA);
            ldsm4(al, aYlo + koA);
#pragma unroll
            for (int nt = 0; nt < 8; nt++) {
                uint32_t bh[4];
                ldsm4(bh, bW + nt * (16 * 80) + koB);
                mma16816(oacc[nt * 2], ah, bh + 0);
                mma16816(oacc[nt * 2 + 1], ah, bh + 2);
                mma16816(oacc[nt * 2], al, bh + 0);
                mma16816(oacc[nt * 2 + 1], al, bh + 2);
            }
        }
        __syncthreads();
    }

    const int r0 = s * 16 + (lane >> 2);
    const int c0 = hs * 128 + (lane & 3) * 2;
    float* oR0 = out + (size_t)(R0 + r0) * DD + c0;
    float* oR1 = oR0 + 8 * DD;
#pragma unroll
    for (int nt = 0; nt < 16; nt++) {
        const float2 bv = *(const float2*)(bvec + c0 + nt * 8);
        float v0 = oacc[nt][0] + bv.x, v1 = oacc[nt][1] + bv.y;
        float v2 = oacc[nt][2] + bv.x, v3 = oacc[nt][3] + bv.y;
        v0 = v0 > 0.f ? v0 : 0.01f * v0;
        v1 = v1 > 0.f ? v1 : 0.01f * v1;
        v2 = v2 > 0.f ? v2 : 0.01f * v2;
        v3 = v3 > 0.f ? v3 : 0.01f * v3;
        *(float2*)(oR0 + nt * 8) = make_float2(v0, v1);
        *(float2*)(oR1 + nt * 8) = make_float2(v2, v3);
    }
}

// ---------------------------------------------------------------------------
extern "C" void kernel_launch(void* const* d_in, const int* in_sizes, int n_in,
                              void* d_out, int out_size) {
    const float* inp = (const float*)d_in[0];
    const float* adj = (const float*)d_in[1];
    const float* W = (const float*)d_in[2];
    const float* b = (const float*)d_in[3];
    float* out = (float*)d_out;

    norm_kernel<<<BN / 8, 256>>>(inp);
    split_x_kernel<<<dim3(NN / 32, DD / 32, BB), dim3(32, 8)>>>(inp);
    split_wt_kernel<<<dim3(DD / 32, DD / 32), dim3(32, 8)>>>(W);

    cudaFuncSetAttribute(s_kernel, cudaFuncAttributeMaxDynamicSharedMemorySize, SMEM_S);
    s_kernel<<<BB * 32 * 2, 256, SMEM_S>>>(adj);

    cudaFuncSetAttribute(pv_kernel, cudaFuncAttributeMaxDynamicSharedMemorySize, SMEM_PV);
    pv_kernel<<<BB * 32, 256, SMEM_PV>>>();

    cudaFuncSetAttribute(ywb_kernel, cudaFuncAttributeMaxDynamicSharedMemorySize, SMEM_YW);
    ywb_kernel<<<BN / 64, 256, SMEM_YW>>>(b, out);
}

// round 16
// speedup vs baseline: 1.0891x; 1.0234x over previous
#include <cuda_runtime.h>
#include <cuda_fp16.h>
#include <stdint.h>

#define BB 8
#define NN 2048
#define DD 256
#define BN (BB * NN)
#define TM 32            // PV chunk
#define TMS 64           // S-kernel chunk
#define NCH_S 16         // S chunks per half

// ---------------- device scratch (allocation-free) ----------------
__device__ __half g_xhi[BN * DD];        // X row-major fp16
__device__ __half g_xthi[BB * DD * NN];  // X^T [b][k][m] fp16
__device__ __half g_wthi[DD * DD];       // W^T [n][k] fp16
__device__ __half g_p[(size_t)BN * NN];  // P' = shifted exp * adj, fp16
__device__ float g_den[2 * BN];          // per-half denominators (scaled)
__device__ float g_sh2[BN];              // per-row exponent shift (log2 units)

// ---------------- helpers ----------------
__device__ __forceinline__ uint32_t smem_u32(const void* p) {
    uint32_t a;
    asm("{ .reg .u64 t; cvta.to.shared.u64 t, %1; cvt.u32.u64 %0, t; }" : "=r"(a) : "l"(p));
    return a;
}
__device__ __forceinline__ void ldsm4(uint32_t* r, uint32_t a) {
    asm volatile("ldmatrix.sync.aligned.m8n8.x4.shared.b16 {%0,%1,%2,%3}, [%4];"
                 : "=r"(r[0]), "=r"(r[1]), "=r"(r[2]), "=r"(r[3]) : "r"(a));
}
__device__ __forceinline__ void mma16816(float* c, const uint32_t* a, const uint32_t* b) {
    asm volatile("mma.sync.aligned.m16n8k16.row.col.f32.f16.f16.f32 "
                 "{%0,%1,%2,%3},{%4,%5,%6,%7},{%8,%9},{%0,%1,%2,%3};"
                 : "+f"(c[0]), "+f"(c[1]), "+f"(c[2]), "+f"(c[3])
                 : "r"(a[0]), "r"(a[1]), "r"(a[2]), "r"(a[3]), "r"(b[0]), "r"(b[1]));
}
#define CPA16(dst, src) \
    asm volatile("cp.async.cg.shared.global [%0], [%1], 16;" :: "r"(dst), "l"(src))
#define CP_COMMIT() asm volatile("cp.async.commit_group;")
#define CP_WAIT(n)  asm volatile("cp.async.wait_group %0;" :: "n"(n))

__device__ __forceinline__ uint32_t cvt2h(float lo, float hi) {
    uint32_t r;
    asm("cvt.rn.f16x2.f32 %0, %1, %2;" : "=r"(r) : "f"(hi), "f"(lo));
    return r;
}
__device__ __forceinline__ float2 h2f2(uint32_t u) {
    __half2 h = *(__half2*)&u;
    return __half22float2(h);
}
__device__ __forceinline__ float fexp16s(float s, float sh) {
    float r;
    asm("ex2.approx.f32 %0, %1;" : "=f"(r) : "f"(fmaf(s, 0.09016844005556021f, -sh)));
    return r;
}
// streaming (evict-first) global ops for touch-once data
__device__ __forceinline__ float2 ldcs2(const float* p) {
    float2 v;
    asm volatile("ld.global.cs.v2.f32 {%0,%1}, [%2];" : "=f"(v.x), "=f"(v.y) : "l"(p));
    return v;
}
__device__ __forceinline__ void stcs32(void* p, uint32_t v) {
    asm volatile("st.global.cs.b32 [%0], %1;" :: "l"(p), "r"(v));
}

// ---------------- preprocessing ----------------
__global__ void __launch_bounds__(256) norm_kernel(const float* __restrict__ inp) {
    const int row = blockIdx.x * 8 + (threadIdx.x >> 5);
    const int lane = threadIdx.x & 31;
    const float4* p = (const float4*)(inp + (size_t)row * DD);
    const float4 a = p[lane];
    const float4 b = p[lane + 32];
    float s = a.x * a.x + a.y * a.y + a.z * a.z + a.w * a.w +
              b.x * b.x + b.y * b.y + b.z * b.z + b.w * b.w;
#pragma unroll
    for (int o = 16; o > 0; o >>= 1) s += __shfl_xor_sync(0xFFFFFFFFu, s, o);
    if (lane == 0)
        g_sh2[row] = (s * 0.0625f - 8.0f) * 1.44269504f;
}

__global__ void __launch_bounds__(256) split_x_kernel(const float* __restrict__ inp) {
    __shared__ float t[32][33];
    const int b = blockIdx.z;
    const int m0 = blockIdx.x * 32, k0 = blockIdx.y * 32;
    const int tx = threadIdx.x, ty = threadIdx.y;
    const float* src = inp + ((size_t)b * NN + m0) * DD + k0;
#pragma unroll
    for (int s = 0; s < 4; s++) {
        const int m = ty + 8 * s;
        const float v = src[(size_t)m * DD + tx];
        t[m][tx] = v;
        g_xhi[((size_t)b * NN + m0 + m) * DD + k0 + tx] = __float2half_rn(v);
    }
    __syncthreads();
#pragma unroll
    for (int s = 0; s < 4; s++) {
        const int c = ty + 8 * s;
        g_xthi[((size_t)b * DD + k0 + c) * NN + m0 + tx] = __float2half_rn(t[tx][c]);
    }
}

__global__ void __launch_bounds__(256) split_wt_kernel(const float* __restrict__ W) {
    __shared__ float t[32][33];
    const int k0 = blockIdx.x * 32, n0 = blockIdx.y * 32;
    const int tx = threadIdx.x, ty = threadIdx.y;
#pragma unroll
    for (int s = 0; s < 4; s++) t[ty + 8 * s][tx] = W[(size_t)(k0 + ty + 8 * s) * DD + n0 + tx];
    __syncthreads();
#pragma unroll
    for (int s = 0; s < 4; s++) {
        const int k = ty + 8 * s;
        g_wthi[(size_t)(n0 + tx) * DD + k0 + k] = __float2half_rn(t[k][tx]);
    }
}

// ---------------- S kernel: P' = ex2(QK^T*c - sh)*adj -> gmem; den ----------------
#define SQ_B0  0u
#define SQ_B1  33792u
#define SQ_B2  67584u
#define SQ_DEN 101376u
#define SMEM_S 101888u

__global__ void __launch_bounds__(256, 2) s_kernel(const float* __restrict__ adj) {
    extern __shared__ char smem[];
    const uint32_t sb = smem_u32(smem);
    const int tid = threadIdx.x;
    const int wid = tid >> 5, lane = tid & 31;
    const int s = wid >> 1, hs = wid & 1;
    const int lane7 = lane & 7, l34 = (lane >> 3) & 1, l4 = lane >> 4;

    const int bb = blockIdx.x >> 6;
    const int i0 = ((blockIdx.x >> 1) & 31) * 64;
    const int half = blockIdx.x & 1;
    const int mbase = half * (NCH_S * TMS);

    const __half* __restrict__ xhiB = g_xhi + (size_t)bb * NN * DD;
    const float* __restrict__ adjB = adj + (size_t)bb * NN * NN;
    __half* __restrict__ pB = g_p + ((size_t)bb * NN + i0) * NN;

    float* den_sm = (float*)(smem + SQ_DEN);
    if (tid < 64) den_sm[tid] = 0.f;

    const int ldRow = tid >> 5, ldC16 = tid & 31;
    const uint32_t kRing[3] = {sb + SQ_B0, sb + SQ_B1, sb + SQ_B2};

    // Q -> ring[2], K(0) -> ring[0], K(1) -> ring[1]
#pragma unroll
    for (int it = 0; it < 8; it++) {
        const int row = ldRow + it * 8;
        CPA16(kRing[2] + row * 528 + ldC16 * 16, xhiB + (size_t)(i0 + row) * DD + ldC16 * 8);
    }
    CP_COMMIT();
#pragma unroll
    for (int it = 0; it < 8; it++) {
        const int row = ldRow + it * 8;
        CPA16(kRing[0] + row * 528 + ldC16 * 16, xhiB + (size_t)(mbase + row) * DD + ldC16 * 8);
    }
    CP_COMMIT();
#pragma unroll
    for (int it = 0; it < 8; it++) {
        const int row = ldRow + it * 8;
        CPA16(kRing[1] + row * 528 + ldC16 * 16, xhiB + (size_t)(mbase + TMS + row) * DD + ldC16 * 8);
    }
    CP_COMMIT();

    CP_WAIT(2);
    __syncthreads();

    // hoist Q fragments into registers; ring[2] freed after first barrier
    uint32_t qf[16][4];
    const uint32_t aQ = kRing[2] + (uint32_t)(s * 16 + lane7 + l34 * 8) * 528 + l4 * 16;
#pragma unroll
    for (int kk = 0; kk < 16; kk++) ldsm4(qf[kk], aQ + kk * 32);

    const uint32_t kFrag = (uint32_t)((hs * 32 + l4 * 8 + lane7) * 528 + l34 * 16);

    const int r0 = s * 16 + (lane >> 2);
    const int cb = hs * 32 + (lane & 3) * 2;
    const float sh0 = g_sh2[(size_t)bb * NN + i0 + r0];
    const float sh1 = g_sh2[(size_t)bb * NN + i0 + r0 + 8];
    float den0 = 0.f, den1 = 0.f;

    int bcur = 0;
    for (int ch = 0; ch < NCH_S; ch++) {
        const int m0 = mbase + ch * TMS;
        CP_WAIT(1);
        __syncthreads();     // single barrier per chunk

        // issue K(ch+2) -> drained ring slot
        {
            const int bnext = (bcur + 2 >= 3) ? bcur - 1 : bcur + 2;
            const int mn = mbase + ((ch + 2) & (NCH_S - 1)) * TMS;
#pragma unroll
            for (int it = 0; it < 8; it++) {
                const int row = ldRow + it * 8;
                CPA16(kRing[bnext] + row * 528 + ldC16 * 16, xhiB + (size_t)(mn + row) * DD + ldC16 * 8);
            }
            CP_COMMIT();
        }

        // adj prefetch (streaming; hidden under S MMAs)
        const float* adjR0 = adjB + (size_t)(i0 + r0) * NN + m0 + cb;
        const float* adjR1 = adjR0 + 8 * NN;
        float2 aj0[4], aj1[4];
#pragma unroll
        for (int nt = 0; nt < 4; nt++) {
            aj0[nt] = ldcs2(adjR0 + nt * 8);
            aj1[nt] = ldcs2(adjR1 + nt * 8);
        }

        // S = Q*K (Q from regs), warp tile 16x32
        const uint32_t kB = kRing[bcur] + kFrag;
        float sacc[4][4];
#pragma unroll
        for (int i = 0; i < 4; i++)
#pragma unroll
            for (int j = 0; j < 4; j++) sacc[i][j] = 0.f;
#pragma unroll
        for (int kk = 0; kk < 16; kk++) {
            const uint32_t ko = kk * 32;
            uint32_t b0[4], b1[4];
            ldsm4(b0, kB + ko);
            ldsm4(b1, kB + 16 * 528 + ko);
            mma16816(sacc[0], qf[kk], b0 + 0);
            mma16816(sacc[1], qf[kk], b0 + 2);
            mma16816(sacc[2], qf[kk], b1 + 0);
            mma16816(sacc[3], qf[kk], b1 + 2);
        }

        // epilogue: P' -> gmem fp16 (streaming); denom
#pragma unroll
        for (int nt = 0; nt < 4; nt++) {
            const float p00 = fexp16s(sacc[nt][0], sh0) * aj0[nt].x;
            const float p01 = fexp16s(sacc[nt][1], sh0) * aj0[nt].y;
            const float p10 = fexp16s(sacc[nt][2], sh1) * aj1[nt].x;
            const float p11 = fexp16s(sacc[nt][3], sh1) * aj1[nt].y;
            den0 += p00 + p01;
            den1 += p10 + p11;
            stcs32(pB + (size_t)r0 * NN + m0 + cb + nt * 8, cvt2h(p00, p01));
            stcs32(pB + (size_t)(r0 + 8) * NN + m0 + cb + nt * 8, cvt2h(p10, p11));
        }

        bcur = (bcur + 1 >= 3) ? 0 : bcur + 1;
    }

    den0 += __shfl_xor_sync(0xFFFFFFFFu, den0, 1);
    den0 += __shfl_xor_sync(0xFFFFFFFFu, den0, 2);
    den1 += __shfl_xor_sync(0xFFFFFFFFu, den1, 1);
    den1 += __shfl_xor_sync(0xFFFFFFFFu, den1, 2);
    __syncthreads();
    if ((lane & 3) == 0) {
        atomicAdd(&den_sm[r0], den0);
        atomicAdd(&den_sm[r0 + 8], den1);
    }
    __syncthreads();
    if (tid < 64)
        g_den[(size_t)half * BN + (size_t)bb * NN + i0 + tid] = den_sm[tid];
}

// ---------------- PV+YW fused: Y = (P'@X)/den, then out = lrelu(Y@W + b) ----------------
// mainloop rings: V 0..61440, P 61440..76800 (triple-buffered)
// epilogue (rings dead): YHI 0, YLO 33792, W0 67584, W1 88064, den 108544
#define PV_V0  0u
#define PV_V1  20480u
#define PV_V2  40960u
#define PV_P0  61440u
#define PV_P1  66560u
#define PV_P2  71680u
#define FE_YHI 0u
#define FE_YLO 33792u
#define FE_W0  67584u
#define FE_W1  88064u
#define FE_DEN 108544u
#define SMEM_PV 108800u

__global__ void __launch_bounds__(256, 2) pv_kernel(const float* __restrict__ bvec,
                                                    float* __restrict__ out) {
    extern __shared__ char smem[];
    const uint32_t sb = smem_u32(smem);
    const int tid = threadIdx.x;
    const int wid = tid >> 5, lane = tid & 31;
    const int rs = wid >> 2, cs = wid & 3;
    const int lane7 = lane & 7, l34 = (lane >> 3) & 1, l4 = lane >> 4;

    const int bb = blockIdx.x >> 5;
    const int i0 = (blockIdx.x & 31) * 64;

    const __half* __restrict__ xthiB = g_xthi + (size_t)bb * DD * NN;
    const __half* __restrict__ pB = g_p + ((size_t)bb * NN + i0) * NN;

    const int ldRowV = tid >> 2, ldC16V = tid & 3;
    const int ldRowP = tid >> 2, ldC16P = tid & 3;

    const uint32_t vRing[3] = {sb + PV_V0, sb + PV_V1, sb + PV_V2};
    const uint32_t pRing[3] = {sb + PV_P0, sb + PV_P1, sb + PV_P2};

    // G0: V(0), P(0); G1: V(1), P(1)
#pragma unroll
    for (int it = 0; it < 4; it++) {
        const int row = ldRowV + it * 64;
        CPA16(vRing[0] + row * 80 + ldC16V * 16, xthiB + (size_t)row * NN + ldC16V * 8);
    }
    CPA16(pRing[0] + ldRowP * 80 + ldC16P * 16, pB + (size_t)ldRowP * NN + ldC16P * 8);
    CP_COMMIT();
#pragma unroll
    for (int it = 0; it < 4; it++) {
        const int row = ldRowV + it * 64;
        CPA16(vRing[1] + row * 80 + ldC16V * 16, xthiB + (size_t)row * NN + TM + ldC16V * 8);
    }
    CPA16(pRing[1] + ldRowP * 80 + ldC16P * 16, pB + (size_t)ldRowP * NN + TM + ldC16P * 8);
    CP_COMMIT();

    const uint32_t pFrag = (uint32_t)((rs * 32 + lane7 + l34 * 8) * 80 + l4 * 16);
    const uint32_t vFrag = (uint32_t)((cs * 64 + l4 * 8 + lane7) * 80 + l34 * 16);

    float oacc[16][4];
#pragma unroll
    for (int i = 0; i < 16; i++)
#pragma unroll
        for (int j = 0; j < 4; j++) oacc[i][j] = 0.f;

    int bcur = 0;
    for (int ch = 0; ch < 64; ch++) {
        CP_WAIT(1);
        __syncthreads();

        {
            const int bnext = (bcur + 2 >= 3) ? bcur - 1 : bcur + 2;
            const int mn = ((ch + 2) & 63) * TM;
#pragma unroll
            for (int it = 0; it < 4; it++) {
                const int row = ldRowV + it * 64;
                CPA16(vRing[bnext] + row * 80 + ldC16V * 16, xthiB + (size_t)row * NN + mn + ldC16V * 8);
            }
            CPA16(pRing[bnext] + ldRowP * 80 + ldC16P * 16, pB + (size_t)ldRowP * NN + mn + ldC16P * 8);
            CP_COMMIT();
        }

        const uint32_t pA = pRing[bcur] + pFrag;
        const uint32_t vB = vRing[bcur] + vFrag;
#pragma unroll
        for (int kk = 0; kk < 2; kk++) {
            const uint32_t ko = kk * 32;
            uint32_t a0[4], a1[4];
            ldsm4(a0, pA + ko);
            ldsm4(a1, pA + 16 * 80 + ko);
#pragma unroll
            for (int j = 0; j < 4; j++) {
                uint32_t bv[4];
                ldsm4(bv, vB + j * (16 * 80) + ko);
                mma16816(oacc[j * 2 + 0], a0, bv + 0);
                mma16816(oacc[j * 2 + 1], a0, bv + 2);
                mma16816(oacc[8 + j * 2 + 0], a1, bv + 0);
                mma16816(oacc[8 + j * 2 + 1], a1, bv + 2);
            }
        }

        bcur = (bcur + 1 >= 3) ? 0 : bcur + 1;
    }

    // ---- fused epilogue: drain rings, reuse smem for Y/W ----
    CP_WAIT(0);
    __syncthreads();    // all MMA reads + stale prefetch writes complete

    const int ldRowW = tid >> 2, ldC16W = tid & 3;
    // issue W chunk 0 (k 0..31)
#pragma unroll
    for (int it = 0; it < 4; it++) {
        const int row = ldRowW + it * 64;
        CPA16(sb + FE_W0 + row * 80 + ldC16W * 16, g_wthi + (size_t)row * DD + ldC16W * 8);
    }
    CP_COMMIT();

    float* invd_s = (float*)(smem + FE_DEN);
    if (tid < 64) {
        const size_t gi = (size_t)bb * NN + i0 + tid;
        const float d = g_den[gi] + g_den[BN + gi];
        const float eps = 1e-10f * exp2f(-g_sh2[gi]);
        invd_s[tid] = 1.0f / (d + eps);
    }
    __syncthreads();    // invd visible

    // normalize oacc -> fp16 hi/lo Y tiles in smem (ywb layout, stride 528)
#pragma unroll
    for (int t = 0; t < 2; t++) {
        const int rloc = rs * 32 + t * 16 + (lane >> 2);
        const float iv0 = invd_s[rloc];
        const float iv1 = invd_s[rloc + 8];
#pragma unroll
        for (int j = 0; j < 4; j++) {
#pragma unroll
            for (int nn = 0; nn < 2; nn++) {
                const int idx = t * 8 + j * 2 + nn;
                const int col = cs * 64 + j * 16 + nn * 8 + (lane & 3) * 2;
                const float y0 = oacc[idx][0] * iv0, y1 = oacc[idx][1] * iv0;
                const float y2 = oacc[idx][2] * iv1, y3 = oacc[idx][3] * iv1;
                const uint32_t h0 = cvt2h(y0, y1), h1 = cvt2h(y2, y3);
                const float2 f0 = h2f2(h0), f1 = h2f2(h1);
                *(uint32_t*)(smem + FE_YHI + rloc * 528 + col * 2) = h0;
                *(uint32_t*)(smem + FE_YHI + (rloc + 8) * 528 + col * 2) = h1;
                *(uint32_t*)(smem + FE_YLO + rloc * 528 + col * 2) = cvt2h(y0 - f0.x, y1 - f0.y);
                *(uint32_t*)(smem + FE_YLO + (rloc + 8) * 528 + col * 2) = cvt2h(y2 - f1.x, y3 - f1.y);
            }
        }
    }

    // ywb-style warp mapping for the small GEMM
    const int s2 = wid >> 1, hs2 = wid & 1;
    const int aRow = s2 * 16 + lane7 + l34 * 8;
    const uint32_t aYhi = sb + FE_YHI + aRow * 528 + l4 * 16;
    const uint32_t aYlo = sb + FE_YLO + aRow * 528 + l4 * 16;
    const int wRow = hs2 * 128 + l4 * 8 + lane7;
    const uint32_t wFragBase = (uint32_t)(wRow * 80 + l34 * 16);
    const uint32_t wOff[2] = {FE_W0, FE_W1};

    float wacc[16][4];
#pragma unroll
    for (int i = 0; i < 16; i++)
#pragma unroll
        for (int j = 0; j < 4; j++) wacc[i][j] = 0.f;

    for (int kc = 0; kc < 8; kc++) {
        if (kc < 7) {
            const uint32_t wb = wOff[(kc + 1) & 1];
#pragma unroll
            for (int it = 0; it < 4; it++) {
                const int row = ldRowW + it * 64;
                CPA16(sb + wb + row * 80 + ldC16W * 16, g_wthi + (size_t)row * DD + (kc + 1) * 32 + ldC16W * 8);
            }
            CP_COMMIT();
            CP_WAIT(1);
        } else {
            CP_WAIT(0);
        }
        __syncthreads();   // W(kc) ready; (kc=0) also orders Y tiles

        const uint32_t bW = sb + wOff[kc & 1] + wFragBase;
#pragma unroll
        for (int kk = 0; kk < 2; kk++) {
            const uint32_t koA = (kc * 32 + kk * 16) * 2;
            const uint32_t koB = kk * 32;
            uint32_t ah[4], al[4];
            ldsm4(ah, aYhi + koA);
            ldsm4(al, aYlo + koA);
#pragma unroll
            for (int nt = 0; nt < 8; nt++) {
                uint32_t bh[4];
                ldsm4(bh, bW + nt * (16 * 80) + koB);
                mma16816(wacc[nt * 2], ah, bh + 0);
                mma16816(wacc[nt * 2 + 1], ah, bh + 2);
                mma16816(wacc[nt * 2], al, bh + 0);
                mma16816(wacc[nt * 2 + 1], al, bh + 2);
            }
        }
        __syncthreads();
    }

    // bias + leaky relu + store
    const int r0o = s2 * 16 + (lane >> 2);
    const int c0o = hs2 * 128 + (lane & 3) * 2;
    float* oR0 = out + (size_t)((size_t)bb * NN + i0 + r0o) * DD + c0o;
    float* oR1 = oR0 + 8 * DD;
#pragma unroll
    for (int nt = 0; nt < 16; nt++) {
        const float2 bv = *(const float2*)(bvec + c0o + nt * 8);
        float v0 = wacc[nt][0] + bv.x, v1 = wacc[nt][1] + bv.y;
        float v2 = wacc[nt][2] + bv.x, v3 = wacc[nt][3] + bv.y;
        v0 = v0 > 0.f ? v0 : 0.01f * v0;
        v1 = v1 > 0.f ? v1 : 0.01f * v1;
        v2 = v2 > 0.f ? v2 : 0.01f * v2;
        v3 = v3 > 0.f ? v3 : 0.01f * v3;
        *(float2*)(oR0 + nt * 8) = make_float2(v0, v1);
        *(float2*)(oR1 + nt * 8) = make_float2(v2, v3);
    }
}

// ---------------------------------------------------------------------------
extern "C" void kernel_launch(void* const* d_in, const int* in_sizes, int n_in,
                              void* d_out, int out_size) {
    const float* inp = (const float*)d_in[0];
    const float* adj = (const float*)d_in[1];
    const float* W = (const float*)d_in[2];
    const float* b = (const float*)d_in[3];
    float* out = (float*)d_out;

    norm_kernel<<<BN / 8, 256>>>(inp);
    split_x_kernel<<<dim3(NN / 32, DD / 32, BB), dim3(32, 8)>>>(inp);
    split_wt_kernel<<<dim3(DD / 32, DD / 32), dim3(32, 8)>>>(W);

    cudaFuncSetAttribute(s_kernel, cudaFuncAttributeMaxDynamicSharedMemorySize, SMEM_S);
    s_kernel<<<BB * 32 * 2, 256, SMEM_S>>>(adj);

    cudaFuncSetAttribute(pv_kernel, cudaFuncAttributeMaxDynamicSharedMemorySize, SMEM_PV);
    pv_kernel<<<BB * 32, 256, SMEM_PV>>>(b, out);
}

// round 17
// speedup vs baseline: 1.1376x; 1.0446x over previous
#include <cuda_runtime.h>
#include <cuda_fp16.h>
#include <stdint.h>

#define BB 8
#define NN 2048
#define DD 256
#define BN (BB * NN)
#define TM 32            // PV chunk
#define TMS 64           // S chunk
#define NCH_A 32         // S chunks (full m-range)

// ---------------- device scratch (allocation-free) ----------------
__device__ __half g_xhi[BN * DD];        // X row-major fp16
__device__ __half g_xthi[BB * DD * NN];  // X^T [b][k][m] fp16
__device__ __half g_wthi[DD * DD];       // W^T [n][k] fp16
__device__ __half g_p[(size_t)BN * NN];  // P' fp16 (L2-resident between phases)
__device__ float g_sh2[BN];              // per-row exponent shift (log2 units)

// ---------------- helpers ----------------
__device__ __forceinline__ uint32_t smem_u32(const void* p) {
    uint32_t a;
    asm("{ .reg .u64 t; cvta.to.shared.u64 t, %1; cvt.u32.u64 %0, t; }" : "=r"(a) : "l"(p));
    return a;
}
__device__ __forceinline__ void ldsm4(uint32_t* r, uint32_t a) {
    asm volatile("ldmatrix.sync.aligned.m8n8.x4.shared.b16 {%0,%1,%2,%3}, [%4];"
                 : "=r"(r[0]), "=r"(r[1]), "=r"(r[2]), "=r"(r[3]) : "r"(a));
}
__device__ __forceinline__ void mma16816(float* c, const uint32_t* a, const uint32_t* b) {
    asm volatile("mma.sync.aligned.m16n8k16.row.col.f32.f16.f16.f32 "
                 "{%0,%1,%2,%3},{%4,%5,%6,%7},{%8,%9},{%0,%1,%2,%3};"
                 : "+f"(c[0]), "+f"(c[1]), "+f"(c[2]), "+f"(c[3])
                 : "r"(a[0]), "r"(a[1]), "r"(a[2]), "r"(a[3]), "r"(b[0]), "r"(b[1]));
}
#define CPA16(dst, src) \
    asm volatile("cp.async.cg.shared.global [%0], [%1], 16;" :: "r"(dst), "l"(src))
#define CP_COMMIT() asm volatile("cp.async.commit_group;")
#define CP_WAIT(n)  asm volatile("cp.async.wait_group %0;" :: "n"(n))

__device__ __forceinline__ uint32_t cvt2h(float lo, float hi) {
    uint32_t r;
    asm("cvt.rn.f16x2.f32 %0, %1, %2;" : "=r"(r) : "f"(hi), "f"(lo));
    return r;
}
__device__ __forceinline__ float2 h2f2(uint32_t u) {
    __half2 h = *(__half2*)&u;
    return __half22float2(h);
}
__device__ __forceinline__ float fexp16s(float s, float sh) {
    float r;
    asm("ex2.approx.f32 %0, %1;" : "=f"(r) : "f"(fmaf(s, 0.09016844005556021f, -sh)));
    return r;
}
__device__ __forceinline__ float2 ldcs2(const float* p) {
    float2 v;
    asm volatile("ld.global.cs.v2.f32 {%0,%1}, [%2];" : "=f"(v.x), "=f"(v.y) : "l"(p));
    return v;
}

// ---------------- preprocessing ----------------
__global__ void __launch_bounds__(256) norm_kernel(const float* __restrict__ inp) {
    const int row = blockIdx.x * 8 + (threadIdx.x >> 5);
    const int lane = threadIdx.x & 31;
    const float4* p = (const float4*)(inp + (size_t)row * DD);
    const float4 a = p[lane];
    const float4 b = p[lane + 32];
    float s = a.x * a.x + a.y * a.y + a.z * a.z + a.w * a.w +
              b.x * b.x + b.y * b.y + b.z * b.z + b.w * b.w;
#pragma unroll
    for (int o = 16; o > 0; o >>= 1) s += __shfl_xor_sync(0xFFFFFFFFu, s, o);
    if (lane == 0)
        g_sh2[row] = (s * 0.0625f - 8.0f) * 1.44269504f;
}

__global__ void __launch_bounds__(256) split_x_kernel(const float* __restrict__ inp) {
    __shared__ float t[32][33];
    const int b = blockIdx.z;
    const int m0 = blockIdx.x * 32, k0 = blockIdx.y * 32;
    const int tx = threadIdx.x, ty = threadIdx.y;
    const float* src = inp + ((size_t)b * NN + m0) * DD + k0;
#pragma unroll
    for (int s = 0; s < 4; s++) {
        const int m = ty + 8 * s;
        const float v = src[(size_t)m * DD + tx];
        t[m][tx] = v;
        g_xhi[((size_t)b * NN + m0 + m) * DD + k0 + tx] = __float2half_rn(v);
    }
    __syncthreads();
#pragma unroll
    for (int s = 0; s < 4; s++) {
        const int c = ty + 8 * s;
        g_xthi[((size_t)b * DD + k0 + c) * NN + m0 + tx] = __float2half_rn(t[tx][c]);
    }
}

__global__ void __launch_bounds__(256) split_wt_kernel(const float* __restrict__ W) {
    __shared__ float t[32][33];
    const int k0 = blockIdx.x * 32, n0 = blockIdx.y * 32;
    const int tx = threadIdx.x, ty = threadIdx.y;
#pragma unroll
    for (int s = 0; s < 4; s++) t[ty + 8 * s][tx] = W[(size_t)(k0 + ty + 8 * s) * DD + n0 + tx];
    __syncthreads();
#pragma unroll
    for (int s = 0; s < 4; s++) {
        const int k = ty + 8 * s;
        g_wthi[(size_t)(n0 + tx) * DD + k0 + k] = __float2half_rn(t[k][tx]);
    }
}

// ---------------- fused attention: phase A (S->P'), phase B (PV), epilogue (YW) ----------------
// Phase A: K ring 3x33792 = 0..101376
// Phase B: V ring 3x20480 = 0..61440, P ring 3x5120 = 61440..76800
// Epilogue: YHI 0..33792, YLO 33792..67584, W0/W1 67584..108544
// den/invd: 108544..108800 (disjoint from all phases)
#define FA_B0  0u
#define FA_B1  33792u
#define FA_B2  67584u
#define PV_V0  0u
#define PV_V1  20480u
#define PV_V2  40960u
#define PV_P0  61440u
#define PV_P1  66560u
#define PV_P2  71680u
#define FE_YHI 0u
#define FE_YLO 33792u
#define FE_W0  67584u
#define FE_W1  88064u
#define F_DEN  108544u
#define SMEM_F 108800u

__global__ void __launch_bounds__(256, 2) fused_kernel(const float* __restrict__ adj,
                                                       const float* __restrict__ bvec,
                                                       float* __restrict__ out) {
    extern __shared__ char smem[];
    const uint32_t sb = smem_u32(smem);
    const int tid = threadIdx.x;
    const int wid = tid >> 5, lane = tid & 31;
    const int lane7 = lane & 7, l34 = (lane >> 3) & 1, l4 = lane >> 4;

    const int bb = blockIdx.x >> 5;
    const int i0 = (blockIdx.x & 31) * 64;

    const __half* __restrict__ xhiB = g_xhi + (size_t)bb * NN * DD;
    const __half* __restrict__ xthiB = g_xthi + (size_t)bb * DD * NN;
    const float* __restrict__ adjB = adj + (size_t)bb * NN * NN;
    __half* __restrict__ pB = g_p + ((size_t)bb * NN + i0) * NN;

    float* den_sm = (float*)(smem + F_DEN);
    if (tid < 64) den_sm[tid] = 0.f;

    // ================= PHASE A: S -> P' =================
    {
        const int s = wid >> 1, hs = wid & 1;
        const int ldRow = tid >> 5, ldC16 = tid & 31;
        const uint32_t kRing[3] = {sb + FA_B0, sb + FA_B1, sb + FA_B2};

        // Q -> ring[2], K(0) -> ring[0], K(1) -> ring[1]
#pragma unroll
        for (int it = 0; it < 8; it++) {
            const int row = ldRow + it * 8;
            CPA16(kRing[2] + row * 528 + ldC16 * 16, xhiB + (size_t)(i0 + row) * DD + ldC16 * 8);
        }
        CP_COMMIT();
#pragma unroll
        for (int it = 0; it < 8; it++) {
            const int row = ldRow + it * 8;
            CPA16(kRing[0] + row * 528 + ldC16 * 16, xhiB + (size_t)row * DD + ldC16 * 8);
        }
        CP_COMMIT();
#pragma unroll
        for (int it = 0; it < 8; it++) {
            const int row = ldRow + it * 8;
            CPA16(kRing[1] + row * 528 + ldC16 * 16, xhiB + (size_t)(TMS + row) * DD + ldC16 * 8);
        }
        CP_COMMIT();

        CP_WAIT(2);
        __syncthreads();

        // hoist Q fragments into registers; ring[2] freed after first loop barrier
        uint32_t qf[16][4];
        const uint32_t aQ = kRing[2] + (uint32_t)(s * 16 + lane7 + l34 * 8) * 528 + l4 * 16;
#pragma unroll
        for (int kk = 0; kk < 16; kk++) ldsm4(qf[kk], aQ + kk * 32);

        const uint32_t kFrag = (uint32_t)((hs * 32 + l4 * 8 + lane7) * 528 + l34 * 16);

        const int r0 = s * 16 + (lane >> 2);
        const int cb = hs * 32 + (lane & 3) * 2;
        const float sh0 = g_sh2[(size_t)bb * NN + i0 + r0];
        const float sh1 = g_sh2[(size_t)bb * NN + i0 + r0 + 8];
        float den0 = 0.f, den1 = 0.f;

        int bcur = 0;
        for (int ch = 0; ch < NCH_A; ch++) {
            const int m0 = ch * TMS;
            CP_WAIT(1);
            __syncthreads();     // single barrier per chunk

            // issue K(ch+2) -> drained ring slot
            {
                const int bnext = (bcur + 2 >= 3) ? bcur - 1 : bcur + 2;
                const int mn = ((ch + 2) & (NCH_A - 1)) * TMS;
#pragma unroll
                for (int it = 0; it < 8; it++) {
                    const int row = ldRow + it * 8;
                    CPA16(kRing[bnext] + row * 528 + ldC16 * 16, xhiB + (size_t)(mn + row) * DD + ldC16 * 8);
                }
                CP_COMMIT();
            }

            // adj prefetch (streaming)
            const float* adjR0 = adjB + (size_t)(i0 + r0) * NN + m0 + cb;
            const float* adjR1 = adjR0 + 8 * NN;
            float2 aj0[4], aj1[4];
#pragma unroll
            for (int nt = 0; nt < 4; nt++) {
                aj0[nt] = ldcs2(adjR0 + nt * 8);
                aj1[nt] = ldcs2(adjR1 + nt * 8);
            }

            // S = Q*K (Q from regs), warp tile 16x32
            const uint32_t kB = kRing[bcur] + kFrag;
            float sacc[4][4];
#pragma unroll
            for (int i = 0; i < 4; i++)
#pragma unroll
                for (int j = 0; j < 4; j++) sacc[i][j] = 0.f;
#pragma unroll
            for (int kk = 0; kk < 16; kk++) {
                const uint32_t ko = kk * 32;
                uint32_t b0[4], b1[4];
                ldsm4(b0, kB + ko);
                ldsm4(b1, kB + 16 * 528 + ko);
                mma16816(sacc[0], qf[kk], b0 + 0);
                mma16816(sacc[1], qf[kk], b0 + 2);
                mma16816(sacc[2], qf[kk], b1 + 0);
                mma16816(sacc[3], qf[kk], b1 + 2);
            }

            // epilogue: P' -> gmem fp16 (default policy -> L2 resident); denom
#pragma unroll
            for (int nt = 0; nt < 4; nt++) {
                const float p00 = fexp16s(sacc[nt][0], sh0) * aj0[nt].x;
                const float p01 = fexp16s(sacc[nt][1], sh0) * aj0[nt].y;
                const float p10 = fexp16s(sacc[nt][2], sh1) * aj1[nt].x;
                const float p11 = fexp16s(sacc[nt][3], sh1) * aj1[nt].y;
                den0 += p00 + p01;
                den1 += p10 + p11;
                *(uint32_t*)(pB + (size_t)r0 * NN + m0 + cb + nt * 8) = cvt2h(p00, p01);
                *(uint32_t*)(pB + (size_t)(r0 + 8) * NN + m0 + cb + nt * 8) = cvt2h(p10, p11);
            }

            bcur = (bcur + 1 >= 3) ? 0 : bcur + 1;
        }

        // denominators -> invd in smem
        den0 += __shfl_xor_sync(0xFFFFFFFFu, den0, 1);
        den0 += __shfl_xor_sync(0xFFFFFFFFu, den0, 2);
        den1 += __shfl_xor_sync(0xFFFFFFFFu, den1, 1);
        den1 += __shfl_xor_sync(0xFFFFFFFFu, den1, 2);
        CP_WAIT(0);          // drain stale K prefetches before smem reuse
        __syncthreads();
        if ((lane & 3) == 0) {
            atomicAdd(&den_sm[r0], den0);
            atomicAdd(&den_sm[r0 + 8], den1);
        }
        __syncthreads();     // den complete; P' writes visible CTA-wide
        if (tid < 64) {
            const float eps = 1e-10f * exp2f(-g_sh2[(size_t)bb * NN + i0 + tid]);
            den_sm[tid] = 1.0f / (den_sm[tid] + eps);
        }
        __syncthreads();     // invd ready; K rings drained
    }

    // ================= PHASE B: Y = (P' @ X) / den =================
    const int rs = wid >> 2, cs = wid & 3;
    const int ldRowV = tid >> 2, ldC16V = tid & 3;

    const uint32_t vRing[3] = {sb + PV_V0, sb + PV_V1, sb + PV_V2};
    const uint32_t pRing[3] = {sb + PV_P0, sb + PV_P1, sb + PV_P2};

#pragma unroll
    for (int it = 0; it < 4; it++) {
        const int row = ldRowV + it * 64;
        CPA16(vRing[0] + row * 80 + ldC16V * 16, xthiB + (size_t)row * NN + ldC16V * 8);
    }
    CPA16(pRing[0] + ldRowV * 80 + ldC16V * 16, pB + (size_t)ldRowV * NN + ldC16V * 8);
    CP_COMMIT();
#pragma unroll
    for (int it = 0; it < 4; it++) {
        const int row = ldRowV + it * 64;
        CPA16(vRing[1] + row * 80 + ldC16V * 16, xthiB + (size_t)row * NN + TM + ldC16V * 8);
    }
    CPA16(pRing[1] + ldRowV * 80 + ldC16V * 16, pB + (size_t)ldRowV * NN + TM + ldC16V * 8);
    CP_COMMIT();

    const uint32_t pFrag = (uint32_t)((rs * 32 + lane7 + l34 * 8) * 80 + l4 * 16);
    const uint32_t vFrag = (uint32_t)((cs * 64 + l4 * 8 + lane7) * 80 + l34 * 16);

    float oacc[16][4];
#pragma unroll
    for (int i = 0; i < 16; i++)
#pragma unroll
        for (int j = 0; j < 4; j++) oacc[i][j] = 0.f;

    int bcur = 0;
    for (int ch = 0; ch < 64; ch++) {
        CP_WAIT(1);
        __syncthreads();

        {
            const int bnext = (bcur + 2 >= 3) ? bcur - 1 : bcur + 2;
            const int mn = ((ch + 2) & 63) * TM;
#pragma unroll
            for (int it = 0; it < 4; it++) {
                const int row = ldRowV + it * 64;
                CPA16(vRing[bnext] + row * 80 + ldC16V * 16, xthiB + (size_t)row * NN + mn + ldC16V * 8);
            }
            CPA16(pRing[bnext] + ldRowV * 80 + ldC16V * 16, pB + (size_t)ldRowV * NN + mn + ldC16V * 8);
            CP_COMMIT();
        }

        const uint32_t pA = pRing[bcur] + pFrag;
        const uint32_t vB = vRing[bcur] + vFrag;
#pragma unroll
        for (int kk = 0; kk < 2; kk++) {
            const uint32_t ko = kk * 32;
            uint32_t a0[4], a1[4];
            ldsm4(a0, pA + ko);
            ldsm4(a1, pA + 16 * 80 + ko);
#pragma unroll
            for (int j = 0; j < 4; j++) {
                uint32_t bv[4];
                ldsm4(bv, vB + j * (16 * 80) + ko);
                mma16816(oacc[j * 2 + 0], a0, bv + 0);
                mma16816(oacc[j * 2 + 1], a0, bv + 2);
                mma16816(oacc[8 + j * 2 + 0], a1, bv + 0);
                mma16816(oacc[8 + j * 2 + 1], a1, bv + 2);
            }
        }

        bcur = (bcur + 1 >= 3) ? 0 : bcur + 1;
    }

    // ================= EPILOGUE: out = lrelu(Y @ W + b) =================
    CP_WAIT(0);
    __syncthreads();    // rings drained

    const int ldRowW = tid >> 2, ldC16W = tid & 3;
#pragma unroll
    for (int it = 0; it < 4; it++) {
        const int row = ldRowW + it * 64;
        CPA16(sb + FE_W0 + row * 80 + ldC16W * 16, g_wthi + (size_t)row * DD + ldC16W * 8);
    }
    CP_COMMIT();

    float* invd_s = den_sm;  // already holds invd

    // normalize oacc -> fp16 hi/lo Y tiles in smem
#pragma unroll
    for (int t = 0; t < 2; t++) {
        const int rloc = rs * 32 + t * 16 + (lane >> 2);
        const float iv0 = invd_s[rloc];
        const float iv1 = invd_s[rloc + 8];
#pragma unroll
        for (int j = 0; j < 4; j++) {
#pragma unroll
            for (int nn = 0; nn < 2; nn++) {
                const int idx = t * 8 + j * 2 + nn;
                const int col = cs * 64 + j * 16 + nn * 8 + (lane & 3) * 2;
                const float y0 = oacc[idx][0] * iv0, y1 = oacc[idx][1] * iv0;
                const float y2 = oacc[idx][2] * iv1, y3 = oacc[idx][3] * iv1;
                const uint32_t h0 = cvt2h(y0, y1), h1 = cvt2h(y2, y3);
                const float2 f0 = h2f2(h0), f1 = h2f2(h1);
                *(uint32_t*)(smem + FE_YHI + rloc * 528 + col * 2) = h0;
                *(uint32_t*)(smem + FE_YHI + (rloc + 8) * 528 + col * 2) = h1;
                *(uint32_t*)(smem + FE_YLO + rloc * 528 + col * 2) = cvt2h(y0 - f0.x, y1 - f0.y);
                *(uint32_t*)(smem + FE_YLO + (rloc + 8) * 528 + col * 2) = cvt2h(y2 - f1.x, y3 - f1.y);
            }
        }
    }

    const int s2 = wid >> 1, hs2 = wid & 1;
    const int aRow = s2 * 16 + lane7 + l34 * 8;
    const uint32_t aYhi = sb + FE_YHI + aRow * 528 + l4 * 16;
    const uint32_t aYlo = sb + FE_YLO + aRow * 528 + l4 * 16;
    const int wRow = hs2 * 128 + l4 * 8 + lane7;
    const uint32_t wFragBase = (uint32_t)(wRow * 80 + l34 * 16);
    const uint32_t wOff[2] = {FE_W0, FE_W1};

    float wacc[16][4];
#pragma unroll
    for (int i = 0; i < 16; i++)
#pragma unroll
        for (int j = 0; j < 4; j++) wacc[i][j] = 0.f;

    for (int kc = 0; kc < 8; kc++) {
        if (kc < 7) {
            const uint32_t wb = wOff[(kc + 1) & 1];
#pragma unroll
            for (int it = 0; it < 4; it++) {
                const int row = ldRowW + it * 64;
                CPA16(sb + wb + row * 80 + ldC16W * 16, g_wthi + (size_t)row * DD + (kc + 1) * 32 + ldC16W * 8);
            }
            CP_COMMIT();
            CP_WAIT(1);
        } else {
            CP_WAIT(0);
        }
        __syncthreads();   // W(kc) ready; (kc=0) also orders Y tiles

        const uint32_t bW = sb + wOff[kc & 1] + wFragBase;
#pragma unroll
        for (int kk = 0; kk < 2; kk++) {
            const uint32_t koA = (kc * 32 + kk * 16) * 2;
            const uint32_t koB = kk * 32;
            uint32_t ah[4], al[4];
            ldsm4(ah, aYhi + koA);
            ldsm4(al, aYlo + koA);
#pragma unroll
            for (int nt = 0; nt < 8; nt++) {
                uint32_t bh[4];
                ldsm4(bh, bW + nt * (16 * 80) + koB);
                mma16816(wacc[nt * 2], ah, bh + 0);
                mma16816(wacc[nt * 2 + 1], ah, bh + 2);
                mma16816(wacc[nt * 2], al, bh + 0);
                mma16816(wacc[nt * 2 + 1], al, bh + 2);
            }
        }
        __syncthreads();
    }

    const int r0o = s2 * 16 + (lane >> 2);
    const int c0o = hs2 * 128 + (lane & 3) * 2;
    float* oR0 = out + (size_t)((size_t)bb * NN + i0 + r0o) * DD + c0o;
    float* oR1 = oR0 + 8 * DD;
#pragma unroll
    for (int nt = 0; nt < 16; nt++) {
        const float2 bv = *(const float2*)(bvec + c0o + nt * 8);
        float v0 = wacc[nt][0] + bv.x, v1 = wacc[nt][1] + bv.y;
        float v2 = wacc[nt][2] + bv.x, v3 = wacc[nt][3] + bv.y;
        v0 = v0 > 0.f ? v0 : 0.01f * v0;
        v1 = v1 > 0.f ? v1 : 0.01f * v1;
        v2 = v2 > 0.f ? v2 : 0.01f * v2;
        v3 = v3 > 0.f ? v3 : 0.01f * v3;
        *(float2*)(oR0 + nt * 8) = make_float2(v0, v1);
        *(float2*)(oR1 + nt * 8) = make_float2(v2, v3);
    }
}

// ---------------------------------------------------------------------------
extern "C" void kernel_launch(void* const* d_in, const int* in_sizes, int n_in,
                              void* d_out, int out_size) {
    const float* inp = (const float*)d_in[0];
    const float* adj = (const float*)d_in[1];
    const float* W = (const float*)d_in[2];
    const float* b = (const float*)d_in[3];
    float* out = (float*)d_out;

    norm_kernel<<<BN / 8, 256>>>(inp);
    split_x_kernel<<<dim3(NN / 32, DD / 32, BB), dim3(32, 8)>>>(inp);
    split_wt_kernel<<<dim3(DD / 32, DD / 32), dim3(32, 8)>>>(W);

    cudaFuncSetAttribute(fused_kernel, cudaFuncAttributeMaxDynamicSharedMemorySize, SMEM_F);
    fused_kernel<<<BB * 32, 256, SMEM_F>>>(adj, b, out);
}